// round 10
// baseline (speedup 1.0000x reference)
#include <cuda_runtime.h>
#include <cstdint>

#define B_ 1024
#define T_ 256
#define D_ 64
#define H_ 128
#define RR 4
#define NCTA (B_ / RR)   // 256

// Precomputed x-projections (pre-activation, bias included).
__device__ float g_xg[(size_t)B_ * T_ * 256];   // gate: r cols 0..127, u cols 128..255
__device__ float g_xc[(size_t)B_ * T_ * 128];   // candidate
__device__ int   g_perm[B_];                    // rows sorted by len desc

// ---- packed f32x2 helpers ----
__device__ __forceinline__ unsigned long long pack2(float lo, float hi) {
    unsigned long long r;
    asm("mov.b64 %0, {%1, %2};" : "=l"(r) : "f"(lo), "f"(hi));
    return r;
}
__device__ __forceinline__ void fma2(unsigned long long& acc,
                                     unsigned long long a,
                                     unsigned long long b) {
    asm("fma.rn.f32x2 %0, %1, %2, %0;" : "+l"(acc) : "l"(a), "l"(b));
}
__device__ __forceinline__ float sum2(unsigned long long a) {
    float lo, hi;
    asm("mov.b64 {%0, %1}, %2;" : "=f"(lo), "=f"(hi) : "l"(a));
    return lo + hi;
}
__device__ __forceinline__ float sigmoidf(float s) { return 1.f / (1.f + __expf(-s)); }
__device__ __forceinline__ float tanh_safe(float s) {
    const float sc = fminf(fmaxf(s, -15.f), 15.f);
    const float e  = __expf(2.f * sc);
    return (e - 1.f) / (e + 1.f);
}

// named-barrier producer/consumer sync (384 = all threads in CTA)
#define BSYNC(id)   asm volatile("bar.sync %0, 384;"   :: "r"(id) : "memory")
#define BARRIVE(id) asm volatile("bar.arrive %0, 384;" :: "r"(id) : "memory")

// ============================================================================
// Sort rows by seq_len descending (counting sort, one CTA).
// ============================================================================
__global__ void sort_rows(const int* __restrict__ seq_lens) {
    __shared__ int base[T_ + 1];
    const int tid = threadIdx.x;          // 1024 threads
    if (tid <= T_) base[tid] = 0;
    __syncthreads();
    const int len = seq_lens[tid];
    atomicAdd(&base[len], 1);
    __syncthreads();
    if (tid == 0) {                        // descending prefix
        int acc = 0;
        for (int l = T_; l >= 0; l--) { int c = base[l]; base[l] = acc; acc += c; }
    }
    __syncthreads();
    const int pos = atomicAdd(&base[len], 1);
    g_perm[pos] = tid;
}

// ============================================================================
// Phase A: time-parallel x-projections. Weights in regs, x via LDS.128.
// ============================================================================
__global__ __launch_bounds__(384)
void gru_phaseA(const int* __restrict__ item_his,
                const int* __restrict__ seq_lens,
                const float* __restrict__ emb,
                const float* __restrict__ Wg,
                const float* __restrict__ bg,
                const float* __restrict__ Wc,
                const float* __restrict__ bc)
{
    const int b  = blockIdx.y;
    const int t0 = blockIdx.x * 64;
    const int len = seq_lens[b];
    if (t0 >= len) return;
    const int nt = min(64, len - t0);
    const int tid = threadIdx.x;

    __shared__ int idx_sh[64];
    __shared__ __align__(16) float x_sh[64 * 64];

    unsigned long long wp[32];
    float bias;
    if (tid < 256) {
        bias = bg[tid];
#pragma unroll
        for (int i = 0; i < 32; i++)
            wp[i] = pack2(Wg[(2 * i) * 256 + tid], Wg[(2 * i + 1) * 256 + tid]);
    } else {
        const int c = tid - 256;
        bias = bc[c];
#pragma unroll
        for (int i = 0; i < 32; i++)
            wp[i] = pack2(Wc[(2 * i) * 128 + c], Wc[(2 * i + 1) * 128 + c]);
    }

    if (tid < nt) idx_sh[tid] = item_his[b * T_ + t0 + tid];
    __syncthreads();

    {   // coalesced gather: nt embedding rows of 256B each
        const float4* e4 = (const float4*)emb;
        float4* x4 = (float4*)x_sh;
        for (int i = tid; i < nt * 16; i += 384) {
            const int r = i >> 4, q = i & 15;
            x4[r * 16 + q] = e4[(size_t)idx_sh[r] * 16 + q];
        }
    }
    __syncthreads();

    const ulonglong2* x2 = (const ulonglong2*)x_sh;
    for (int r = 0; r < nt; r += 2) {
        const bool two = (r + 1 < nt);
        unsigned long long a0 = 0ULL, a1 = 0ULL, b0 = 0ULL, b1 = 0ULL;
#pragma unroll
        for (int i = 0; i < 16; i++) {
            ulonglong2 xx = x2[r * 16 + i];
            fma2(a0, xx.x, wp[2 * i]);
            fma2(a1, xx.y, wp[2 * i + 1]);
            if (two) {
                ulonglong2 yy = x2[(r + 1) * 16 + i];
                fma2(b0, yy.x, wp[2 * i]);
                fma2(b1, yy.y, wp[2 * i + 1]);
            }
        }
        const float acc0 = sum2(a0) + sum2(a1) + bias;
        const size_t p0 = (size_t)b * T_ + t0 + r;
        if (tid < 256) __stcs(&g_xg[p0 * 256 + tid], acc0);
        else           __stcs(&g_xc[p0 * 128 + (tid - 256)], acc0);
        if (two) {
            const float acc1 = sum2(b0) + sum2(b1) + bias;
            if (tid < 256) __stcs(&g_xg[(p0 + 1) * 256 + tid], acc1);
            else           __stcs(&g_xc[(p0 + 1) * 128 + (tid - 256)], acc1);
        }
    }
}

// ============================================================================
// Phase B: decoupled producer/consumer recurrence, 4 sorted rows per CTA.
//   k-split weight layout: lane pair (2p,2p+1) co-owns cols {2p,2p+1};
//   even lane holds k[0:64), odd k[64:128). Each h LDS.128 feeds 4 FMA2.
//   One shfl.xor(1) per row completes the dot; each lane activates col==tid.
//   gate (256 thr): sync(1) G_A arrive(3) | sync(2) G_B arrive(4)
//   cand (128 thr): sync(3) C_A arrive(1) | sync(4) C_B arrive(2)
// ============================================================================
__device__ __forceinline__ void dotpair(const ulonglong2* __restrict__ hp,
                                        const unsigned long long* __restrict__ wA,
                                        const unsigned long long* __restrict__ wB,
                                        float& s0, float& s1)
{
    unsigned long long a0 = 0ULL, a1 = 0ULL, b0 = 0ULL, b1 = 0ULL;
#pragma unroll
    for (int i = 0; i < 16; i++) {
        ulonglong2 hv = hp[i];                  // LDS.128: 4 floats of my k-half
        fma2(a0, hv.x, wA[2 * i]);
        fma2(a1, hv.y, wA[2 * i + 1]);
        fma2(b0, hv.x, wB[2 * i]);
        fma2(b1, hv.y, wB[2 * i + 1]);
    }
    s0 = sum2(a0) + sum2(a1);
    s1 = sum2(b0) + sum2(b1);
}

// combine k-halves across the lane pair; returns full dot for col = my tid
__device__ __forceinline__ float combine(float s0, float s1, int kh)
{
    const float send = kh ? s0 : s1;            // partial of partner's column
    const float recv = __shfl_xor_sync(0xffffffffu, send, 1);
    return (kh ? s1 : s0) + recv;
}

__global__ __launch_bounds__(384, 1)
void gru_phaseB(const int* __restrict__ seq_lens,
                const float* __restrict__ Wg,
                const float* __restrict__ Wc,
                float* __restrict__ out)
{
    __shared__ __align__(16) float h[RR][128];
    __shared__ __align__(16) float rh[RR][128];
    __shared__ float uu[RR][128];

    const int tid = threadIdx.x;
    const int cta = blockIdx.x;
    const int g0  = cta * RR;

    const bool isGate = tid < 256;
    const int  j      = isGate ? tid : tid - 256;   // my column (= lane identity)
    const int  kh     = j & 1;                      // my k-half
    const int  c0     = j & ~1;                     // column pair base
    const int  S      = isGate ? 256 : 128;

    int len[RR], off[RR];
#pragma unroll
    for (int r = 0; r < RR; r++) {
        const int b = g_perm[g0 + r];
        len[r] = seq_lens[b];
        off[r] = b * (T_ * S) + j;
    }
    const int tmax = len[0];

    for (int i = tid; i < RR * 128; i += 384) ((float*)h)[i] = 0.f;
    __syncthreads();

    if (tmax > 0) {
        const float* xbase = isGate ? g_xg : g_xc;

        // weights: 2 columns x 32 k-pairs of my k-half
        unsigned long long wA[32], wB[32];
        {
            const float* W   = isGate ? Wg : Wc;
            const int    kb  = 64 + kh * 64;        // recurrent rows start at 64
#pragma unroll
            for (int i = 0; i < 32; i++) {
                const int k = kb + 2 * i;
                wA[i] = pack2(W[k * S + c0],     W[(k + 1) * S + c0]);
                wB[i] = pack2(W[k * S + c0 + 1], W[(k + 1) * S + c0 + 1]);
            }
        }
        // FIX (R8 bug): a k-half is 64 floats = 16 ulonglong2, not 8.
        const int hoff = kh * 16;                   // ulonglong2 offset of my k-half

        float q[RR];
#pragma unroll
        for (int r = 0; r < RR; r++)
            q[r] = (0 < len[r]) ? __ldcs(&xbase[off[r]]) : 0.f;

        // cand pre-arms the h-ready barriers (h zeroed + synced above)
        if (!isGate) { BARRIVE(1); BARRIVE(2); }

        for (int t = 0; t < tmax; t++) {
            if (isGate) {
                // ---- G_A(t): rows 0,1 ----
                BSYNC(1);
                {
                    const float x0 = q[0], x1 = q[1];
                    q[0] = (t + 1 < len[0]) ? __ldcs(&xbase[off[0] + S]) : 0.f;
                    q[1] = (t + 1 < len[1]) ? __ldcs(&xbase[off[1] + S]) : 0.f;
                    float sa, sb, sc, sd;
                    dotpair((const ulonglong2*)h[0] + hoff, wA, wB, sa, sb);
                    dotpair((const ulonglong2*)h[1] + hoff, wA, wB, sc, sd);
                    const float f0 = combine(sa, sb, kh) + x0;
                    const float f1 = combine(sc, sd, kh) + x1;
                    {
                        const float g = sigmoidf(f0);
                        if (j < 128) rh[0][j] = g * h[0][j]; else uu[0][j - 128] = g;
                    }
                    if (t < len[1]) {
                        const float g = sigmoidf(f1);
                        if (j < 128) rh[1][j] = g * h[1][j]; else uu[1][j - 128] = g;
                    }
                }
                BARRIVE(3);
                // ---- G_B(t): rows 2,3 ----
                BSYNC(2);
                {
                    const float x2 = q[2], x3 = q[3];
                    q[2] = (t + 1 < len[2]) ? __ldcs(&xbase[off[2] + S]) : 0.f;
                    q[3] = (t + 1 < len[3]) ? __ldcs(&xbase[off[3] + S]) : 0.f;
                    if (t < len[2]) {
                        float sa, sb, sc, sd;
                        dotpair((const ulonglong2*)h[2] + hoff, wA, wB, sa, sb);
                        dotpair((const ulonglong2*)h[3] + hoff, wA, wB, sc, sd);
                        const float f2 = combine(sa, sb, kh) + x2;
                        const float f3 = combine(sc, sd, kh) + x3;
                        {
                            const float g = sigmoidf(f2);
                            if (j < 128) rh[2][j] = g * h[2][j]; else uu[2][j - 128] = g;
                        }
                        if (t < len[3]) {
                            const float g = sigmoidf(f3);
                            if (j < 128) rh[3][j] = g * h[3][j]; else uu[3][j - 128] = g;
                        }
                    }
                }
                BARRIVE(4);
            } else {
                // ---- C_A(t): rows 0,1 ----
                BSYNC(3);
                {
                    const float x0 = q[0], x1 = q[1];
                    q[0] = (t + 1 < len[0]) ? __ldcs(&xbase[off[0] + S]) : 0.f;
                    q[1] = (t + 1 < len[1]) ? __ldcs(&xbase[off[1] + S]) : 0.f;
                    float sa, sb, sc, sd;
                    dotpair((const ulonglong2*)rh[0] + hoff, wA, wB, sa, sb);
                    dotpair((const ulonglong2*)rh[1] + hoff, wA, wB, sc, sd);
                    const float f0 = combine(sa, sb, kh) + x0;
                    const float f1 = combine(sc, sd, kh) + x1;
                    {
                        const float c = tanh_safe(f0);
                        const float u = uu[0][j];
                        h[0][j] = u * h[0][j] + (1.f - u) * c;
                    }
                    if (t < len[1]) {
                        const float c = tanh_safe(f1);
                        const float u = uu[1][j];
                        h[1][j] = u * h[1][j] + (1.f - u) * c;
                    }
                }
                if (t + 1 < tmax) BARRIVE(1);
                // ---- C_B(t): rows 2,3 ----
                BSYNC(4);
                {
                    const float x2 = q[2], x3 = q[3];
                    q[2] = (t + 1 < len[2]) ? __ldcs(&xbase[off[2] + S]) : 0.f;
                    q[3] = (t + 1 < len[3]) ? __ldcs(&xbase[off[3] + S]) : 0.f;
                    if (t < len[2]) {
                        float sa, sb, sc, sd;
                        dotpair((const ulonglong2*)rh[2] + hoff, wA, wB, sa, sb);
                        dotpair((const ulonglong2*)rh[3] + hoff, wA, wB, sc, sd);
                        const float f2 = combine(sa, sb, kh) + x2;
                        const float f3 = combine(sc, sd, kh) + x3;
                        {
                            const float c = tanh_safe(f2);
                            const float u = uu[2][j];
                            h[2][j] = u * h[2][j] + (1.f - u) * c;
                        }
                        if (t < len[3]) {
                            const float c = tanh_safe(f3);
                            const float u = uu[3][j];
                            h[3][j] = u * h[3][j] + (1.f - u) * c;
                        }
                    }
                }
                if (t + 1 < tmax) BARRIVE(2);
            }

#pragma unroll
            for (int r = 0; r < RR; r++) off[r] += S;
        }
        __syncthreads();
    }

    for (int i = tid; i < RR * 128; i += 384) {
        const int r = i >> 7;
        out[g_perm[g0 + r] * 128 + (i & 127)] = h[r][i & 127];
    }
}

// ============================================================================
extern "C" void kernel_launch(void* const* d_in, const int* in_sizes, int n_in,
                              void* d_out, int out_size)
{
    const int*   item_his = (const int*)d_in[0];
    const int*   seq_lens = (const int*)d_in[1];
    const float* emb      = (const float*)d_in[2];
    const float* Wg       = (const float*)d_in[3];
    const float* bg       = (const float*)d_in[4];
    const float* Wc       = (const float*)d_in[5];
    const float* bc       = (const float*)d_in[6];
    float* out = (float*)d_out;

    sort_rows<<<1, B_>>>(seq_lens);
    dim3 gA(T_ / 64, B_);   // (4, 1024)
    gru_phaseA<<<gA, 384>>>(item_his, seq_lens, emb, Wg, bg, Wc, bc);
    gru_phaseB<<<NCTA, 384>>>(seq_lens, Wg, Wc, out);
}